// round 1
// baseline (speedup 1.0000x reference)
#include <cuda_runtime.h>
#include <cstdint>

// Problem constants
#define Hh 512
#define Bb 64
#define Ss 2048
#define BS (Bb*Ss)   // 131072 rows

// Scratch (no cudaMalloc allowed)
__device__ float g_Wt[Hh*Hh];          // W_w transposed: Wt[k][h]
__device__ float g_ubb[Bb*Hh];         // u + U_b + W_b per (b,h)
__device__ float g_energy[BS];         // pre-softmax energies
__device__ float g_ctx[Bb*16*Hh];      // context partials (16 s-chunks)

// ---------------- small prep kernels ----------------

__global__ void k_transpose(const float* __restrict__ W) {
    __shared__ float t[32][33];
    int x = blockIdx.x*32 + threadIdx.x;   // k index in W row
    int y = blockIdx.y*32 + threadIdx.y;   // h index (row of W)
    t[threadIdx.y][threadIdx.x] = W[y*Hh + x];
    __syncthreads();
    int ox = blockIdx.y*32 + threadIdx.x;  // h
    int oy = blockIdx.x*32 + threadIdx.y;  // k
    g_Wt[oy*Hh + ox] = t[threadIdx.x][threadIdx.y];
}

__global__ void k_ubb(const float* __restrict__ hid,
                      const float* __restrict__ Uw,
                      const float* __restrict__ Ub,
                      const float* __restrict__ Wb) {
    int b = blockIdx.x;
    int h = threadIdx.x;                    // 512 threads
    __shared__ float hs[Hh];
    hs[h] = hid[b*Hh + h];                  // hidden[-1] == hidden[0] (L=1)
    __syncthreads();
    const float4* row = reinterpret_cast<const float4*>(Uw + (size_t)h*Hh);
    const float4* hv  = reinterpret_cast<const float4*>(hs);
    float acc = 0.f;
    #pragma unroll 4
    for (int k = 0; k < Hh/4; k++) {
        float4 r = row[k]; float4 x = hv[k];
        acc += r.x*x.x + r.y*x.y + r.z*x.z + r.w*x.w;
    }
    g_ubb[b*Hh + h] = acc + Ub[h] + Wb[h];
}

__global__ void k_zero_energy() {
    int i = blockIdx.x*blockDim.x + threadIdx.x;
    if (i < BS) g_energy[i] = 0.f;
}

// ---------------- main fused energy GEMM ----------------
// energy[r] += sum_{col in tile} V[col] * tanh( (enc @ W^T)[r,col] + ubb[b,col] )
// Tile: 128 rows x 128 cols, K chunked by 16. 256 threads, 8x8 microtile.

__global__ void __launch_bounds__(256, 2)
k_energy(const float* __restrict__ enc, const float* __restrict__ Vw) {
    __shared__ float As[16][128];
    __shared__ float Bs[16][128];

    const int row0 = blockIdx.x * 128;       // global row (b*S + s)
    const int col0 = blockIdx.y * 128;       // h-out chunk
    const int tid  = threadIdx.x;
    const int tx   = tid & 15;               // col group
    const int ty   = tid >> 4;               // row group

    float acc[8][8];
    #pragma unroll
    for (int i = 0; i < 8; i++)
        #pragma unroll
        for (int j = 0; j < 8; j++) acc[i][j] = 0.f;

    const int ar = tid >> 2;                 // 0..63 (2 passes of 64 rows)
    const int ak = (tid & 3) * 4;
    const int bk = tid >> 5;                 // 0..7 (2 passes of 8 k-rows)
    const int bc = (tid & 31) * 4;

    for (int kc = 0; kc < Hh; kc += 16) {
        #pragma unroll
        for (int p = 0; p < 2; p++) {
            int r = ar + p*64;
            float4 v = *reinterpret_cast<const float4*>(
                enc + (size_t)(row0 + r)*Hh + kc + ak);
            As[ak+0][r] = v.x; As[ak+1][r] = v.y;
            As[ak+2][r] = v.z; As[ak+3][r] = v.w;
        }
        #pragma unroll
        for (int p = 0; p < 2; p++) {
            int k = bk + p*8;
            *reinterpret_cast<float4*>(&Bs[k][bc]) =
                *reinterpret_cast<const float4*>(g_Wt + (size_t)(kc + k)*Hh + col0 + bc);
        }
        __syncthreads();
        #pragma unroll
        for (int k = 0; k < 16; k++) {
            float4 a0 = *reinterpret_cast<const float4*>(&As[k][ty*8]);
            float4 a1 = *reinterpret_cast<const float4*>(&As[k][ty*8+4]);
            float4 b0 = *reinterpret_cast<const float4*>(&Bs[k][tx*8]);
            float4 b1 = *reinterpret_cast<const float4*>(&Bs[k][tx*8+4]);
            float a[8] = {a0.x,a0.y,a0.z,a0.w,a1.x,a1.y,a1.z,a1.w};
            float b[8] = {b0.x,b0.y,b0.z,b0.w,b1.x,b1.y,b1.z,b1.w};
            #pragma unroll
            for (int i = 0; i < 8; i++)
                #pragma unroll
                for (int j = 0; j < 8; j++)
                    acc[i][j] += a[i]*b[j];
        }
        __syncthreads();
    }

    // fused epilogue: tanh + V-dot, partial reduce over this CTA's 128 cols
    const int b = row0 / Ss;                 // 128 | 2048, tile never spans b
    float ub[8], vv[8];
    #pragma unroll
    for (int j = 0; j < 8; j++) {
        int col = col0 + tx*8 + j;
        ub[j] = g_ubb[b*Hh + col];
        vv[j] = Vw[col];
    }
    float e[8];
    #pragma unroll
    for (int i = 0; i < 8; i++) {
        float s = 0.f;
        #pragma unroll
        for (int j = 0; j < 8; j++)
            s += vv[j] * tanhf(acc[i][j] + ub[j]);
        e[i] = s;
    }
    // reduce across the 16 tx lanes (warp halves)
    #pragma unroll
    for (int off = 8; off > 0; off >>= 1)
        #pragma unroll
        for (int i = 0; i < 8; i++)
            e[i] += __shfl_down_sync(0xffffffffu, e[i], off, 16);
    if (tx == 0) {
        #pragma unroll
        for (int i = 0; i < 8; i++)
            atomicAdd(&g_energy[row0 + ty*8 + i], e[i]);
    }
}

// ---------------- softmax over S per batch ----------------
__global__ void k_softmax(float* __restrict__ attn) {
    const int b = blockIdx.x;
    const int tid = threadIdx.x;             // 256
    __shared__ float red[256];
    float v[8];
    float mx = -1e30f;
    #pragma unroll
    for (int i = 0; i < 8; i++) {
        v[i] = g_energy[b*Ss + tid + i*256];
        mx = fmaxf(mx, v[i]);
    }
    red[tid] = mx; __syncthreads();
    for (int o = 128; o > 0; o >>= 1) {
        if (tid < o) red[tid] = fmaxf(red[tid], red[tid+o]);
        __syncthreads();
    }
    mx = red[0]; __syncthreads();
    float sum = 0.f;
    #pragma unroll
    for (int i = 0; i < 8; i++) { v[i] = __expf(v[i] - mx); sum += v[i]; }
    red[tid] = sum; __syncthreads();
    for (int o = 128; o > 0; o >>= 1) {
        if (tid < o) red[tid] += red[tid+o];
        __syncthreads();
    }
    float inv = 1.f / red[0];
    #pragma unroll
    for (int i = 0; i < 8; i++)
        attn[b*Ss + tid + i*256] = v[i] * inv;
}

// ---------------- context = attn @ enc ----------------
__global__ void k_ctx_part(const float* __restrict__ enc,
                           const float* __restrict__ attn) {
    const int sc = blockIdx.x;               // 0..15
    const int b  = blockIdx.y;
    const int tid = threadIdx.x;             // 256; handles h=tid and tid+256
    const int s0 = sc*128;
    const float* ab = attn + b*Ss + s0;
    const float* eb = enc + ((size_t)(b*Ss + s0))*Hh;
    float a0 = 0.f, a1 = 0.f;
    #pragma unroll 4
    for (int s = 0; s < 128; s++) {
        float w = ab[s];
        a0 += w * eb[(size_t)s*Hh + tid];
        a1 += w * eb[(size_t)s*Hh + tid + 256];
    }
    g_ctx[(b*16 + sc)*Hh + tid]       = a0;
    g_ctx[(b*16 + sc)*Hh + tid + 256] = a1;
}

__global__ void k_ctx_reduce(float* __restrict__ ctx) {
    const int b = blockIdx.x;
    const int h = threadIdx.x;               // 512
    float s = 0.f;
    #pragma unroll
    for (int sc = 0; sc < 16; sc++)
        s += g_ctx[(b*16 + sc)*Hh + h];
    ctx[b*Hh + h] = s;
}

// ---------------- launch ----------------
extern "C" void kernel_launch(void* const* d_in, const int* in_sizes, int n_in,
                              void* d_out, int out_size) {
    const float* hidden = (const float*)d_in[0];
    const float* enc    = (const float*)d_in[1];
    const float* U_w    = (const float*)d_in[2];
    const float* U_b    = (const float*)d_in[3];
    const float* W_w    = (const float*)d_in[4];
    const float* W_b    = (const float*)d_in[5];
    const float* V_w    = (const float*)d_in[6];
    // V_b shifts all energies equally -> softmax invariant -> unused.

    float* out_ctx  = (float*)d_out;            // [B,H] = 32768 floats
    float* out_attn = out_ctx + Bb*Hh;          // [B,S] = 131072 floats

    k_transpose<<<dim3(16,16), dim3(32,32)>>>(W_w);
    k_ubb<<<Bb, Hh>>>(hidden, U_w, U_b, W_b);
    k_zero_energy<<<(BS+255)/256, 256>>>();
    k_energy<<<dim3(BS/128, Hh/128), 256>>>(enc, V_w);
    k_softmax<<<Bb, 256>>>(out_attn);
    k_ctx_part<<<dim3(16, Bb), 256>>>(enc, out_attn);
    k_ctx_reduce<<<Bb, Hh>>>(out_ctx);
}

// round 4
// speedup vs baseline: 1.8007x; 1.8007x over previous
#include <cuda_runtime.h>
#include <cstdint>

#define Hh 512
#define Bb 64
#define Ss 2048
#define BS (Bb*Ss)   // 131072 rows

// ---------------- device scratch (no cudaMalloc allowed) ----------------
__device__ float g_ubb[Bb*Hh];         // u + U_b + W_b per (b,h)
__device__ float g_energy[BS];         // pre-softmax energies
__device__ float g_ctx[Bb*16*Hh];      // context partials (16 s-chunks)

// ---------------- generic PTX helpers ----------------
__device__ __forceinline__ void cpasync16(uint32_t dst, const void* src) {
    asm volatile("cp.async.cg.shared.global [%0], [%1], 16;\n"
                 :: "r"(dst), "l"(src));
}
__device__ __forceinline__ void cp_commit() {
    asm volatile("cp.async.commit_group;\n" ::: "memory");
}
template<int N> __device__ __forceinline__ void cp_wait() {
    asm volatile("cp.async.wait_group %0;\n" :: "n"(N) : "memory");
}
__device__ __forceinline__ uint32_t smem_u32(const void* p) {
    uint32_t a;
    asm("{ .reg .u64 t; cvta.to.shared.u64 t, %1; cvt.u32.u64 %0, t; }"
        : "=r"(a) : "l"(p));
    return a;
}
__device__ __forceinline__ float tanh_ap(float x) {
    float y;
    asm("tanh.approx.f32 %0, %1;" : "=f"(y) : "f"(x));
    return y;
}
__device__ __forceinline__ void mma_tf32(float* c, const uint32_t* a, const uint32_t* b) {
    asm volatile(
        "mma.sync.aligned.m16n8k8.row.col.f32.tf32.tf32.f32 "
        "{%0,%1,%2,%3}, {%4,%5,%6,%7}, {%8,%9}, {%0,%1,%2,%3};"
        : "+f"(c[0]), "+f"(c[1]), "+f"(c[2]), "+f"(c[3])
        : "r"(a[0]), "r"(a[1]), "r"(a[2]), "r"(a[3]), "r"(b[0]), "r"(b[1]));
}

// SMEM: A stages [2][8][128][4] f32 (16KB each), B stages [2][8][256][4] (32KB each)
#define SMA_STAGE 16384u
#define SMB_OFF   32768u
#define SMB_STAGE 32768u
#define SMEM_TOTAL (32768 + 2*32768)   // 98304

// ---------------- prep: ubb = U(h) + U_b + W_b ----------------
__global__ void k_ubb(const float* __restrict__ hid,
                      const float* __restrict__ Uw,
                      const float* __restrict__ Ub,
                      const float* __restrict__ Wb) {
    int b = blockIdx.x;
    int h = threadIdx.x;                    // 512 threads
    __shared__ float hs[Hh];
    hs[h] = hid[b*Hh + h];
    __syncthreads();
    const float4* row = reinterpret_cast<const float4*>(Uw + (size_t)h*Hh);
    const float4* hv  = reinterpret_cast<const float4*>(hs);
    float acc = 0.f;
    #pragma unroll 4
    for (int k = 0; k < Hh/4; k++) {
        float4 r = row[k]; float4 x = hv[k];
        acc += r.x*x.x + r.y*x.y + r.z*x.z + r.w*x.w;
    }
    g_ubb[b*Hh + h] = acc + Ub[h] + Wb[h];
}

__global__ void k_zero_energy() {
    int i = blockIdx.x*blockDim.x + threadIdx.x;
    if (i < BS) g_energy[i] = 0.f;
}

// ---------------- main: tf32 mma.sync GEMM + fused tanh/V epilogue ----------------
// CTA tile: M=128 (rows of b*S), N=256 (h cols), K=512 chunked by 32.
// 512 threads = 16 warps: warp_m = wid&3 (32 rows), warp_n = wid>>2 (64 cols).
// Smem chunk layout: [k_hi=k/4][row][k_lo=k%4] -> conflict-free frag LDS.

__device__ __forceinline__ void load_chunk(uint32_t sb, const float* enc, const float* Ww,
                                           int row0, int col0, int kc, int stage, int tid) {
    uint32_t abase = sb + (uint32_t)stage * SMA_STAGE;
    uint32_t bbase = sb + SMB_OFF + (uint32_t)stage * SMB_STAGE;
    // A: 128 rows x 32 k = 1024 x 16B
    #pragma unroll
    for (int i = 0; i < 2; i++) {
        int t = tid + i*512;
        int kh = t & 7, r = t >> 3;
        cpasync16(abase + (uint32_t)(kh*2048 + r*16),
                  enc + (size_t)(row0 + r)*Hh + kc + kh*4);
    }
    // B: 256 n x 32 k = 2048 x 16B   (B[n][k] = W[h=n][k], col-major KxN for mma)
    #pragma unroll
    for (int i = 0; i < 4; i++) {
        int t = tid + i*512;
        int kh = t & 7, n = t >> 3;
        cpasync16(bbase + (uint32_t)(kh*4096 + n*16),
                  Ww + (size_t)(col0 + n)*Hh + kc + kh*4);
    }
    cp_commit();
}

__global__ void __launch_bounds__(512, 1)
k_energy(const float* __restrict__ enc,
         const float* __restrict__ Ww,
         const float* __restrict__ Vw) {
    extern __shared__ char smem[];
    uint32_t sb = smem_u32(smem);
    const int tid = threadIdx.x;
    const int wid = tid >> 5, lane = tid & 31;
    const int g = lane >> 2, tig = lane & 3;
    const int warp_m = wid & 3, warp_n = wid >> 2;
    const int m_base = warp_m * 32;          // within 128
    const int n_base = warp_n * 64;          // within 256

    const int row0 = blockIdx.x * 128;       // 16 CTAs per batch: never spans b
    const int col0 = blockIdx.y * 256;
    const int b = row0 / Ss;

    float c[2][8][4];
    #pragma unroll
    for (int mt = 0; mt < 2; mt++)
        #pragma unroll
        for (int nt = 0; nt < 8; nt++)
            #pragma unroll
            for (int j = 0; j < 4; j++) c[mt][nt][j] = 0.f;

    load_chunk(sb, enc, Ww, row0, col0, 0,  0, tid);
    load_chunk(sb, enc, Ww, row0, col0, 32, 1, tid);

    for (int ch = 0; ch < 16; ch++) {
        if (ch < 14) cp_wait<1>(); else cp_wait<0>();
        __syncthreads();

        const uint32_t* As = reinterpret_cast<const uint32_t*>(
            smem + (ch & 1) * SMA_STAGE);
        const uint32_t* Bs = reinterpret_cast<const uint32_t*>(
            smem + SMB_OFF + (ch & 1) * SMB_STAGE);

        #pragma unroll
        for (int kk = 0; kk < 4; kk++) {     // 4 k-steps of 8 within chunk
            const int kh = kk * 2;
            uint32_t a[2][4];
            #pragma unroll
            for (int mt = 0; mt < 2; mt++) {
                int rb = kh*512 + (m_base + mt*16 + g)*4 + tig;
                a[mt][0] = As[rb];
                a[mt][1] = As[rb + 32];
                a[mt][2] = As[rb + 512];
                a[mt][3] = As[rb + 544];
            }
            uint32_t bf[8][2];
            #pragma unroll
            for (int nt = 0; nt < 8; nt++) {
                int nb = kh*1024 + (n_base + nt*8 + g)*4 + tig;
                bf[nt][0] = Bs[nb];
                bf[nt][1] = Bs[nb + 1024];
            }
            #pragma unroll
            for (int mt = 0; mt < 2; mt++)
                #pragma unroll
                for (int nt = 0; nt < 8; nt++)
                    mma_tf32(c[mt][nt], a[mt], bf[nt]);
        }
        __syncthreads();
        if (ch + 2 < 16)
            load_chunk(sb, enc, Ww, row0, col0, (ch + 2)*32, ch & 1, tid);
    }

    // fused epilogue: energy[r] += sum_col V[col]*tanh(C[r,col] + ubb[b,col])
    float ub[8][2], vv[8][2];
    #pragma unroll
    for (int nt = 0; nt < 8; nt++) {
        int cb = col0 + n_base + nt*8 + 2*tig;
        ub[nt][0] = g_ubb[b*Hh + cb];     ub[nt][1] = g_ubb[b*Hh + cb + 1];
        vv[nt][0] = Vw[cb];               vv[nt][1] = Vw[cb + 1];
    }
    #pragma unroll
    for (int mt = 0; mt < 2; mt++) {
        float e0 = 0.f, e1 = 0.f;
        #pragma unroll
        for (int nt = 0; nt < 8; nt++) {
            e0 += vv[nt][0]*tanh_ap(c[mt][nt][0] + ub[nt][0]);
            e0 += vv[nt][1]*tanh_ap(c[mt][nt][1] + ub[nt][1]);
            e1 += vv[nt][0]*tanh_ap(c[mt][nt][2] + ub[nt][0]);
            e1 += vv[nt][1]*tanh_ap(c[mt][nt][3] + ub[nt][1]);
        }
        e0 += __shfl_xor_sync(0xffffffffu, e0, 1);
        e0 += __shfl_xor_sync(0xffffffffu, e0, 2);
        e1 += __shfl_xor_sync(0xffffffffu, e1, 1);
        e1 += __shfl_xor_sync(0xffffffffu, e1, 2);
        if (tig == 0) {
            int r = row0 + m_base + mt*16 + g;
            atomicAdd(&g_energy[r],     e0);
            atomicAdd(&g_energy[r + 8], e1);
        }
    }
}

// ---------------- softmax over S per batch ----------------
__global__ void k_softmax(float* __restrict__ attn) {
    const int b = blockIdx.x;
    const int tid = threadIdx.x;             // 256
    __shared__ float red[256];
    float v[8];
    float mx = -1e30f;
    #pragma unroll
    for (int i = 0; i < 8; i++) {
        v[i] = g_energy[b*Ss + tid + i*256];
        mx = fmaxf(mx, v[i]);
    }
    red[tid] = mx; __syncthreads();
    for (int o = 128; o > 0; o >>= 1) {
        if (tid < o) red[tid] = fmaxf(red[tid], red[tid+o]);
        __syncthreads();
    }
    mx = red[0]; __syncthreads();
    float sum = 0.f;
    #pragma unroll
    for (int i = 0; i < 8; i++) { v[i] = __expf(v[i] - mx); sum += v[i]; }
    red[tid] = sum; __syncthreads();
    for (int o = 128; o > 0; o >>= 1) {
        if (tid < o) red[tid] += red[tid+o];
        __syncthreads();
    }
    float inv = 1.f / red[0];
    #pragma unroll
    for (int i = 0; i < 8; i++)
        attn[b*Ss + tid + i*256] = v[i] * inv;
}

// ---------------- context = attn @ enc ----------------
__global__ void k_ctx_part(const float* __restrict__ enc,
                           const float* __restrict__ attn) {
    const int sc = blockIdx.x;               // 0..15
    const int b  = blockIdx.y;
    const int tid = threadIdx.x;             // 256
    const int s0 = sc*128;
    const float* ab = attn + b*Ss + s0;
    const float* eb = enc + ((size_t)(b*Ss + s0))*Hh;
    float a0 = 0.f, a1 = 0.f;
    #pragma unroll 4
    for (int s = 0; s < 128; s++) {
        float w = ab[s];
        a0 += w * eb[(size_t)s*Hh + tid];
        a1 += w * eb[(size_t)s*Hh + tid + 256];
    }
    g_ctx[(b*16 + sc)*Hh + tid]       = a0;
    g_ctx[(b*16 + sc)*Hh + tid + 256] = a1;
}

__global__ void k_ctx_reduce(float* __restrict__ ctx) {
    const int b = blockIdx.x;
    const int h = threadIdx.x;               // 512
    float s = 0.f;
    #pragma unroll
    for (int sc = 0; sc < 16; sc++)
        s += g_ctx[(b*16 + sc)*Hh + h];
    ctx[b*Hh + h] = s;
}

// ---------------- launch ----------------
extern "C" void kernel_launch(void* const* d_in, const int* in_sizes, int n_in,
                              void* d_out, int out_size) {
    const float* hidden = (const float*)d_in[0];
    const float* enc    = (const float*)d_in[1];
    const float* U_w    = (const float*)d_in[2];
    const float* U_b    = (const float*)d_in[3];
    const float* W_w    = (const float*)d_in[4];
    const float* W_b    = (const float*)d_in[5];
    const float* V_w    = (const float*)d_in[6];
    // V_b shifts all energies equally -> softmax invariant -> unused.

    float* out_ctx  = (float*)d_out;            // [B,H]
    float* out_attn = out_ctx + Bb*Hh;          // [B,S]

    cudaFuncSetAttribute(k_energy,
                         cudaFuncAttributeMaxDynamicSharedMemorySize, SMEM_TOTAL);

    k_ubb<<<Bb, Hh>>>(hidden, U_w, U_b, W_b);
    k_zero_energy<<<(BS+255)/256, 256>>>();
    k_energy<<<dim3(BS/128, Hh/256), 512, SMEM_TOTAL>>>(enc, W_w, V_w);
    k_softmax<<<Bb, 256>>>(out_attn);
    k_ctx_part<<<dim3(16, Bb), 256>>>(enc, out_attn);
    k_ctx_reduce<<<Bb, Hh>>>(out_ctx);
}

// round 6
// speedup vs baseline: 3.5236x; 1.9568x over previous
#include <cuda_runtime.h>
#include <cuda_fp16.h>
#include <cstdint>

#define Hh 512
#define Bb 64
#define Ss 2048
#define BS (Bb*Ss)   // 131072 rows

// ---------------- device scratch (no cudaMalloc allowed) ----------------
__device__ __half g_ench[(size_t)BS*Hh];   // enc in fp16 (128 MB)
__device__ __half g_Wh[Hh*Hh];             // W_w in fp16
__device__ float g_ubb[Bb*Hh];             // u + U_b + W_b per (b,h)
__device__ float g_energy[BS];             // pre-softmax energies
__device__ float g_ctx[Bb*16*Hh];          // context partials

// ---------------- generic PTX helpers ----------------
__device__ __forceinline__ void cpasync16(uint32_t dst, const void* src) {
    asm volatile("cp.async.cg.shared.global [%0], [%1], 16;\n"
                 :: "r"(dst), "l"(src));
}
__device__ __forceinline__ void cp_commit() {
    asm volatile("cp.async.commit_group;\n" ::: "memory");
}
template<int N> __device__ __forceinline__ void cp_wait() {
    asm volatile("cp.async.wait_group %0;\n" :: "n"(N) : "memory");
}
__device__ __forceinline__ uint32_t smem_u32(const void* p) {
    uint32_t a;
    asm("{ .reg .u64 t; cvta.to.shared.u64 t, %1; cvt.u32.u64 %0, t; }"
        : "=r"(a) : "l"(p));
    return a;
}
__device__ __forceinline__ float tanh_ap(float x) {
    float y;
    asm("tanh.approx.f32 %0, %1;" : "=f"(y) : "f"(x));
    return y;
}
__device__ __forceinline__ void ldsm_x4(uint32_t* r, uint32_t addr) {
    asm volatile("ldmatrix.sync.aligned.m8n8.x4.shared.b16 {%0,%1,%2,%3}, [%4];"
                 : "=r"(r[0]), "=r"(r[1]), "=r"(r[2]), "=r"(r[3]) : "r"(addr));
}
__device__ __forceinline__ void mma_f16(float* c, const uint32_t* a,
                                        uint32_t b0, uint32_t b1) {
    asm volatile(
        "mma.sync.aligned.m16n8k16.row.col.f32.f16.f16.f32 "
        "{%0,%1,%2,%3}, {%4,%5,%6,%7}, {%8,%9}, {%0,%1,%2,%3};"
        : "+f"(c[0]), "+f"(c[1]), "+f"(c[2]), "+f"(c[3])
        : "r"(a[0]), "r"(a[1]), "r"(a[2]), "r"(a[3]), "r"(b0), "r"(b1));
}

// SMEM: A 2 stages x 16KB ([blk4][row128][16 halfs, 32B rows, xor-swizzled]),
//       B 2 stages x 32KB ([blk4][n256][16 halfs])
#define SMA_STAGE 16384u
#define SMB_OFF   32768u
#define SMB_STAGE 32768u
#define SMEM_TOTAL (32768 + 2*32768)   // 98304

// ---------------- converts ----------------
__global__ void k_cvt_enc(const float* __restrict__ enc) {
    size_t i = ((size_t)blockIdx.x*blockDim.x + threadIdx.x) * 8;
    const float4* s = reinterpret_cast<const float4*>(enc + i);
    float4 v0 = s[0], v1 = s[1];
    __half2 h[4];
    h[0] = __floats2half2_rn(v0.x, v0.y);
    h[1] = __floats2half2_rn(v0.z, v0.w);
    h[2] = __floats2half2_rn(v1.x, v1.y);
    h[3] = __floats2half2_rn(v1.z, v1.w);
    *reinterpret_cast<uint4*>(g_ench + i) = *reinterpret_cast<uint4*>(h);
}
__global__ void k_cvt_W(const float* __restrict__ W) {
    size_t i = ((size_t)blockIdx.x*blockDim.x + threadIdx.x) * 8;
    const float4* s = reinterpret_cast<const float4*>(W + i);
    float4 v0 = s[0], v1 = s[1];
    __half2 h[4];
    h[0] = __floats2half2_rn(v0.x, v0.y);
    h[1] = __floats2half2_rn(v0.z, v0.w);
    h[2] = __floats2half2_rn(v1.x, v1.y);
    h[3] = __floats2half2_rn(v1.z, v1.w);
    *reinterpret_cast<uint4*>(g_Wh + i) = *reinterpret_cast<uint4*>(h);
}

// ---------------- prep: ubb = U(h) + U_b + W_b ----------------
__global__ void k_ubb(const float* __restrict__ hid,
                      const float* __restrict__ Uw,
                      const float* __restrict__ Ub,
                      const float* __restrict__ Wb) {
    int b = blockIdx.x;
    int h = threadIdx.x;
    __shared__ float hs[Hh];
    hs[h] = hid[b*Hh + h];
    __syncthreads();
    const float4* row = reinterpret_cast<const float4*>(Uw + (size_t)h*Hh);
    const float4* hv  = reinterpret_cast<const float4*>(hs);
    float acc = 0.f;
    #pragma unroll 4
    for (int k = 0; k < Hh/4; k++) {
        float4 r = row[k]; float4 x = hv[k];
        acc += r.x*x.x + r.y*x.y + r.z*x.z + r.w*x.w;
    }
    g_ubb[b*Hh + h] = acc + Ub[h] + Wb[h];
}

__global__ void k_zero_energy() {
    int i = blockIdx.x*blockDim.x + threadIdx.x;
    if (i < BS) g_energy[i] = 0.f;
}

// ---------------- main: fp16 mma + ldmatrix + fused tanh/V epilogue ----------------
// CTA: M=128 rows, N=256 cols, K=512 chunked by 64 (4 k16 blks), 2 stages.
// 512 threads / 16 warps: warp tile m32 x n64 (mt=2 of m16, nt=8 of n8).

__device__ __forceinline__ void load_chunk(uint32_t sb, int row0, int col0,
                                           int kc, int stage, int tid) {
    uint32_t abase = sb + (uint32_t)stage * SMA_STAGE;
    uint32_t bbase = sb + SMB_OFF + (uint32_t)stage * SMB_STAGE;
    #pragma unroll
    for (int i = 0; i < 2; i++) {            // A: 1024 x 16B
        int u = tid + i*512;
        int blk = u >> 8, v = u & 255, r = v >> 1, c16 = v & 1;
        int p16 = c16 ^ ((r >> 2) & 1);
        cpasync16(abase + (uint32_t)(blk*4096 + r*32 + p16*16),
                  g_ench + (size_t)(row0 + r)*Hh + kc + blk*16 + c16*8);
    }
    #pragma unroll
    for (int i = 0; i < 4; i++) {            // B: 2048 x 16B
        int u = tid + i*512;
        int blk = u >> 9, v = u & 511, n = v >> 1, c16 = v & 1;
        int p16 = c16 ^ ((n >> 2) & 1);
        cpasync16(bbase + (uint32_t)(blk*8192 + n*32 + p16*16),
                  g_Wh + (size_t)(col0 + n)*Hh + kc + blk*16 + c16*8);
    }
    cp_commit();
}

__global__ void __launch_bounds__(512, 1)
k_energy(const float* __restrict__ Vw) {
    extern __shared__ char smem[];
    uint32_t sb = smem_u32(smem);
    const int tid = threadIdx.x;
    const int wid = tid >> 5, lane = tid & 31;
    const int g = lane >> 2, tig = lane & 3;
    const int warp_m = wid & 3, warp_n = wid >> 2;
    const int m_base = warp_m * 32;
    const int n_base = warp_n * 64;

    const int row0 = blockIdx.x * 128;       // never spans a batch
    const int col0 = blockIdx.y * 256;
    const int b = row0 / Ss;

    // ldmatrix lane addresses (xor-swizzled 16B chunks in 32B rows)
    const int a_row = m_base + (lane & 15);
    const uint32_t a_sw = (uint32_t)(((lane >> 4) ^ (a_row >> 2)) & 1);
    const uint32_t a_off = (uint32_t)(a_row*32) + a_sw*16;
    const int b_nrow = n_base + (lane & 7) + ((lane >> 1) & 8);
    const uint32_t b_sw = (uint32_t)(((lane >> 3) ^ (b_nrow >> 2)) & 1);
    const uint32_t b_off = (uint32_t)(b_nrow*32) + b_sw*16;

    float c[2][8][4];
    #pragma unroll
    for (int mt = 0; mt < 2; mt++)
        #pragma unroll
        for (int nt = 0; nt < 8; nt++)
            #pragma unroll
            for (int j = 0; j < 4; j++) c[mt][nt][j] = 0.f;

    load_chunk(sb, row0, col0, 0,  0, tid);
    load_chunk(sb, row0, col0, 64, 1, tid);

    for (int ch = 0; ch < 8; ch++) {
        if (ch < 6) cp_wait<1>(); else cp_wait<0>();
        __syncthreads();

        const uint32_t As = sb + (uint32_t)(ch & 1)*SMA_STAGE;
        const uint32_t Bs = sb + SMB_OFF + (uint32_t)(ch & 1)*SMB_STAGE;

        #pragma unroll
        for (int blk = 0; blk < 4; blk++) {
            uint32_t a[2][4];
            ldsm_x4(a[0], As + blk*4096u + a_off);
            ldsm_x4(a[1], As + blk*4096u + a_off + 512u);
            uint32_t bf[8][2];
            #pragma unroll
            for (int p = 0; p < 4; p++) {
                uint32_t r[4];
                ldsm_x4(r, Bs + blk*8192u + b_off + (uint32_t)p*512u);
                bf[2*p][0]   = r[0]; bf[2*p][1]   = r[1];
                bf[2*p+1][0] = r[2]; bf[2*p+1][1] = r[3];
            }
            #pragma unroll
            for (int mt = 0; mt < 2; mt++)
                #pragma unroll
                for (int nt = 0; nt < 8; nt++)
                    mma_f16(c[mt][nt], a[mt], bf[nt][0], bf[nt][1]);
        }
        __syncthreads();
        if (ch + 2 < 8)
            load_chunk(sb, row0, col0, (ch + 2)*64, ch & 1, tid);
    }

    // fused epilogue: energy[r] += sum_col V[col]*tanh(C[r,col] + ubb[b,col])
    float ub[8][2], vv[8][2];
    #pragma unroll
    for (int nt = 0; nt < 8; nt++) {
        int cb = col0 + n_base + nt*8 + 2*tig;
        ub[nt][0] = g_ubb[b*Hh + cb];     ub[nt][1] = g_ubb[b*Hh + cb + 1];
        vv[nt][0] = Vw[cb];               vv[nt][1] = Vw[cb + 1];
    }
    #pragma unroll
    for (int mt = 0; mt < 2; mt++) {
        float e0 = 0.f, e1 = 0.f;
        #pragma unroll
        for (int nt = 0; nt < 8; nt++) {
            e0 += vv[nt][0]*tanh_ap(c[mt][nt][0] + ub[nt][0]);
            e0 += vv[nt][1]*tanh_ap(c[mt][nt][1] + ub[nt][1]);
            e1 += vv[nt][0]*tanh_ap(c[mt][nt][2] + ub[nt][0]);
            e1 += vv[nt][1]*tanh_ap(c[mt][nt][3] + ub[nt][1]);
        }
        e0 += __shfl_xor_sync(0xffffffffu, e0, 1);
        e0 += __shfl_xor_sync(0xffffffffu, e0, 2);
        e1 += __shfl_xor_sync(0xffffffffu, e1, 1);
        e1 += __shfl_xor_sync(0xffffffffu, e1, 2);
        if (tig == 0) {
            int r = row0 + m_base + mt*16 + g;
            atomicAdd(&g_energy[r],     e0);
            atomicAdd(&g_energy[r + 8], e1);
        }
    }
}

// ---------------- softmax over S per batch ----------------
__global__ void k_softmax(float* __restrict__ attn) {
    const int b = blockIdx.x;
    const int tid = threadIdx.x;             // 256
    __shared__ float red[256];
    float v[8];
    float mx = -1e30f;
    #pragma unroll
    for (int i = 0; i < 8; i++) {
        v[i] = g_energy[b*Ss + tid + i*256];
        mx = fmaxf(mx, v[i]);
    }
    red[tid] = mx; __syncthreads();
    for (int o = 128; o > 0; o >>= 1) {
        if (tid < o) red[tid] = fmaxf(red[tid], red[tid+o]);
        __syncthreads();
    }
    mx = red[0]; __syncthreads();
    float sum = 0.f;
    #pragma unroll
    for (int i = 0; i < 8; i++) { v[i] = __expf(v[i] - mx); sum += v[i]; }
    red[tid] = sum; __syncthreads();
    for (int o = 128; o > 0; o >>= 1) {
        if (tid < o) red[tid] += red[tid+o];
        __syncthreads();
    }
    float inv = 1.f / red[0];
    #pragma unroll
    for (int i = 0; i < 8; i++)
        attn[b*Ss + tid + i*256] = v[i] * inv;
}

// ---------------- context = attn @ enc (fp32 enc for accuracy) ----------------
__global__ void k_ctx_part(const float* __restrict__ enc,
                           const float* __restrict__ attn) {
    const int sc = blockIdx.x;
    const int b  = blockIdx.y;
    const int tid = threadIdx.x;             // 256
    const int s0 = sc*128;
    const float* ab = attn + b*Ss + s0;
    const float* eb = enc + ((size_t)(b*Ss + s0))*Hh;
    float a0 = 0.f, a1 = 0.f;
    #pragma unroll 4
    for (int s = 0; s < 128; s++) {
        float w = ab[s];
        a0 += w * eb[(size_t)s*Hh + tid];
        a1 += w * eb[(size_t)s*Hh + tid + 256];
    }
    g_ctx[(b*16 + sc)*Hh + tid]       = a0;
    g_ctx[(b*16 + sc)*Hh + tid + 256] = a1;
}

__global__ void k_ctx_reduce(float* __restrict__ ctx) {
    const int b = blockIdx.x;
    const int h = threadIdx.x;               // 512
    float s = 0.f;
    #pragma unroll
    for (int sc = 0; sc < 16; sc++)
        s += g_ctx[(b*16 + sc)*Hh + h];
    ctx[b*Hh + h] = s;
}

// ---------------- launch ----------------
extern "C" void kernel_launch(void* const* d_in, const int* in_sizes, int n_in,
                              void* d_out, int out_size) {
    const float* hidden = (const float*)d_in[0];
    const float* enc    = (const float*)d_in[1];
    const float* U_w    = (const float*)d_in[2];
    const float* U_b    = (const float*)d_in[3];
    const float* W_w    = (const float*)d_in[4];
    const float* W_b    = (const float*)d_in[5];
    const float* V_w    = (const float*)d_in[6];
    // V_b shifts all energies equally -> softmax invariant -> unused.

    float* out_ctx  = (float*)d_out;            // [B,H]
    float* out_attn = out_ctx + Bb*Hh;          // [B,S]

    cudaFuncSetAttribute(k_energy,
                         cudaFuncAttributeMaxDynamicSharedMemorySize, SMEM_TOTAL);

    unsigned cvt_blocks = (unsigned)(((size_t)BS * Hh) / 8u / 256u);  // 32768
    k_cvt_enc<<<cvt_blocks, 256>>>(enc);
    k_cvt_W<<<Hh*Hh/8/256, 256>>>(W_w);
    k_ubb<<<Bb, Hh>>>(hidden, U_w, U_b, W_b);
    k_zero_energy<<<(BS+255)/256, 256>>>();
    k_energy<<<dim3(BS/128, Hh/256), 512, SMEM_TOTAL>>>(V_w);
    k_softmax<<<Bb, 256>>>(out_attn);
    k_ctx_part<<<dim3(16, Bb), 256>>>(enc, out_attn);
    k_ctx_reduce<<<Bb, Hh>>>(out_ctx);
}

// round 7
// speedup vs baseline: 3.7549x; 1.0656x over previous
#include <cuda_runtime.h>
#include <cuda_fp16.h>
#include <cstdint>

#define Hh 512
#define Bb 64
#define Ss 2048
#define BS (Bb*Ss)   // 131072 rows

// ---------------- device scratch (no cudaMalloc allowed) ----------------
__device__ __half g_ench[(size_t)BS*Hh];   // enc in fp16 (128 MB)
__device__ __half g_Wh[Hh*Hh];             // W_w in fp16
__device__ float g_ubb[Bb*Hh];             // u + U_b + W_b per (b,h)
__device__ float g_energy2[2*BS];          // per-coltile energy partials
__device__ float g_ctx[Bb*64*Hh];          // context partials (16 sc x 4 grp)

// ---------------- generic PTX helpers ----------------
__device__ __forceinline__ void cpasync16(uint32_t dst, const void* src) {
    asm volatile("cp.async.cg.shared.global [%0], [%1], 16;\n"
                 :: "r"(dst), "l"(src));
}
__device__ __forceinline__ void cp_commit() {
    asm volatile("cp.async.commit_group;\n" ::: "memory");
}
template<int N> __device__ __forceinline__ void cp_wait() {
    asm volatile("cp.async.wait_group %0;\n" :: "n"(N) : "memory");
}
__device__ __forceinline__ uint32_t smem_u32(const void* p) {
    uint32_t a;
    asm("{ .reg .u64 t; cvta.to.shared.u64 t, %1; cvt.u32.u64 %0, t; }"
        : "=r"(a) : "l"(p));
    return a;
}
__device__ __forceinline__ float tanh_ap(float x) {
    float y;
    asm("tanh.approx.f32 %0, %1;" : "=f"(y) : "f"(x));
    return y;
}
__device__ __forceinline__ void ldsm_x4(uint32_t* r, uint32_t addr) {
    asm volatile("ldmatrix.sync.aligned.m8n8.x4.shared.b16 {%0,%1,%2,%3}, [%4];"
                 : "=r"(r[0]), "=r"(r[1]), "=r"(r[2]), "=r"(r[3]) : "r"(addr));
}
__device__ __forceinline__ void mma_f16(float* c, const uint32_t* a,
                                        uint32_t b0, uint32_t b1) {
    asm volatile(
        "mma.sync.aligned.m16n8k16.row.col.f32.f16.f16.f32 "
        "{%0,%1,%2,%3}, {%4,%5,%6,%7}, {%8,%9}, {%0,%1,%2,%3};"
        : "+f"(c[0]), "+f"(c[1]), "+f"(c[2]), "+f"(c[3])
        : "r"(a[0]), "r"(a[1]), "r"(a[2]), "r"(a[3]), "r"(b0), "r"(b1));
}

// SMEM: A 2 stages x 16KB ([blk4][row128][16 halfs, 32B rows, xor-swizzled]),
//       B 2 stages x 32KB ([blk4][n256][16 halfs])
#define SMA_STAGE 16384u
#define SMB_OFF   32768u
#define SMB_STAGE 32768u
#define SMEM_TOTAL (32768 + 2*32768)   // 98304

// ---------------- converts ----------------
__global__ void k_cvt_enc(const float* __restrict__ enc) {
    size_t i = ((size_t)blockIdx.x*blockDim.x + threadIdx.x) * 8;
    const float4* s = reinterpret_cast<const float4*>(enc + i);
    float4 v0 = s[0], v1 = s[1];
    __half2 h[4];
    h[0] = __floats2half2_rn(v0.x, v0.y);
    h[1] = __floats2half2_rn(v0.z, v0.w);
    h[2] = __floats2half2_rn(v1.x, v1.y);
    h[3] = __floats2half2_rn(v1.z, v1.w);
    *reinterpret_cast<uint4*>(g_ench + i) = *reinterpret_cast<uint4*>(h);
}
__global__ void k_cvt_W(const float* __restrict__ W) {
    size_t i = ((size_t)blockIdx.x*blockDim.x + threadIdx.x) * 8;
    const float4* s = reinterpret_cast<const float4*>(W + i);
    float4 v0 = s[0], v1 = s[1];
    __half2 h[4];
    h[0] = __floats2half2_rn(v0.x, v0.y);
    h[1] = __floats2half2_rn(v0.z, v0.w);
    h[2] = __floats2half2_rn(v1.x, v1.y);
    h[3] = __floats2half2_rn(v1.z, v1.w);
    *reinterpret_cast<uint4*>(g_Wh + i) = *reinterpret_cast<uint4*>(h);
}

// ---------------- prep: ubb = U(h) + U_b + W_b ----------------
__global__ void k_ubb(const float* __restrict__ hid,
                      const float* __restrict__ Uw,
                      const float* __restrict__ Ub,
                      const float* __restrict__ Wb) {
    int b = blockIdx.x;
    int h = threadIdx.x;
    __shared__ float hs[Hh];
    hs[h] = hid[b*Hh + h];
    __syncthreads();
    const float4* row = reinterpret_cast<const float4*>(Uw + (size_t)h*Hh);
    const float4* hv  = reinterpret_cast<const float4*>(hs);
    float acc = 0.f;
    #pragma unroll 4
    for (int k = 0; k < Hh/4; k++) {
        float4 r = row[k]; float4 x = hv[k];
        acc += r.x*x.x + r.y*x.y + r.z*x.z + r.w*x.w;
    }
    g_ubb[b*Hh + h] = acc + Ub[h] + Wb[h];
}

// ---------------- main: fp16 mma + ldmatrix + fused tanh/V epilogue ----------------
// CTA: M=128 rows, N=256 cols, K=512 chunked by 64 (4 k16 blks), 2 stages.
// grid = (2 coltiles, 1024 rowtiles): the two CTAs sharing an A tile are
// launch-adjacent -> second A read hits L2.

__device__ __forceinline__ void load_chunk(uint32_t sb, int row0, int col0,
                                           int kc, int stage, int tid) {
    uint32_t abase = sb + (uint32_t)stage * SMA_STAGE;
    uint32_t bbase = sb + SMB_OFF + (uint32_t)stage * SMB_STAGE;
    #pragma unroll
    for (int i = 0; i < 2; i++) {            // A: 1024 x 16B
        int u = tid + i*512;
        int blk = u >> 8, v = u & 255, r = v >> 1, c16 = v & 1;
        int p16 = c16 ^ ((r >> 2) & 1);
        cpasync16(abase + (uint32_t)(blk*4096 + r*32 + p16*16),
                  g_ench + (size_t)(row0 + r)*Hh + kc + blk*16 + c16*8);
    }
    #pragma unroll
    for (int i = 0; i < 4; i++) {            // B: 2048 x 16B
        int u = tid + i*512;
        int blk = u >> 9, v = u & 511, n = v >> 1, c16 = v & 1;
        int p16 = c16 ^ ((n >> 2) & 1);
        cpasync16(bbase + (uint32_t)(blk*8192 + n*32 + p16*16),
                  g_Wh + (size_t)(col0 + n)*Hh + kc + blk*16 + c16*8);
    }
    cp_commit();
}

__global__ void __launch_bounds__(512, 1)
k_energy(const float* __restrict__ Vw) {
    extern __shared__ char smem[];
    uint32_t sb = smem_u32(smem);
    const int tid = threadIdx.x;
    const int wid = tid >> 5, lane = tid & 31;
    const int g = lane >> 2, tig = lane & 3;
    const int warp_m = wid & 3, warp_n = wid >> 2;
    const int m_base = warp_m * 32;
    const int n_base = warp_n * 64;

    const int col0 = blockIdx.x * 256;
    const int row0 = blockIdx.y * 128;       // never spans a batch
    const int b = row0 / Ss;

    // ldmatrix lane addresses (xor-swizzled 16B chunks in 32B rows)
    const int a_row = m_base + (lane & 15);
    const uint32_t a_sw = (uint32_t)(((lane >> 4) ^ (a_row >> 2)) & 1);
    const uint32_t a_off = (uint32_t)(a_row*32) + a_sw*16;
    const int b_nrow = n_base + (lane & 7) + ((lane >> 1) & 8);
    const uint32_t b_sw = (uint32_t)(((lane >> 3) ^ (b_nrow >> 2)) & 1);
    const uint32_t b_off = (uint32_t)(b_nrow*32) + b_sw*16;

    float c[2][8][4];
    #pragma unroll
    for (int mt = 0; mt < 2; mt++)
        #pragma unroll
        for (int nt = 0; nt < 8; nt++)
            #pragma unroll
            for (int j = 0; j < 4; j++) c[mt][nt][j] = 0.f;

    load_chunk(sb, row0, col0, 0,  0, tid);
    load_chunk(sb, row0, col0, 64, 1, tid);

    for (int ch = 0; ch < 8; ch++) {
        if (ch < 6) cp_wait<1>(); else cp_wait<0>();
        __syncthreads();

        const uint32_t As = sb + (uint32_t)(ch & 1)*SMA_STAGE;
        const uint32_t Bs = sb + SMB_OFF + (uint32_t)(ch & 1)*SMB_STAGE;

        #pragma unroll
        for (int blk = 0; blk < 4; blk++) {
            uint32_t a[2][4];
            ldsm_x4(a[0], As + blk*4096u + a_off);
            ldsm_x4(a[1], As + blk*4096u + a_off + 512u);
            uint32_t bf[8][2];
            #pragma unroll
            for (int p = 0; p < 4; p++) {
                uint32_t r[4];
                ldsm_x4(r, Bs + blk*8192u + b_off + (uint32_t)p*512u);
                bf[2*p][0]   = r[0]; bf[2*p][1]   = r[1];
                bf[2*p+1][0] = r[2]; bf[2*p+1][1] = r[3];
            }
            #pragma unroll
            for (int mt = 0; mt < 2; mt++)
                #pragma unroll
                for (int nt = 0; nt < 8; nt++)
                    mma_f16(c[mt][nt], a[mt], bf[nt][0], bf[nt][1]);
        }
        __syncthreads();
        if (ch + 2 < 8)
            load_chunk(sb, row0, col0, (ch + 2)*64, ch & 1, tid);
    }

    // fused epilogue: partial energy over this CTA's 256 cols, combined in smem
    __syncthreads();
    float* s_e = reinterpret_cast<float*>(smem);
    if (tid < 128) s_e[tid] = 0.f;
    __syncthreads();

    float ub[8][2], vv[8][2];
    #pragma unroll
    for (int nt = 0; nt < 8; nt++) {
        int cb = col0 + n_base + nt*8 + 2*tig;
        ub[nt][0] = g_ubb[b*Hh + cb];     ub[nt][1] = g_ubb[b*Hh + cb + 1];
        vv[nt][0] = Vw[cb];               vv[nt][1] = Vw[cb + 1];
    }
    #pragma unroll
    for (int mt = 0; mt < 2; mt++) {
        float e0 = 0.f, e1 = 0.f;
        #pragma unroll
        for (int nt = 0; nt < 8; nt++) {
            e0 += vv[nt][0]*tanh_ap(c[mt][nt][0] + ub[nt][0]);
            e0 += vv[nt][1]*tanh_ap(c[mt][nt][1] + ub[nt][1]);
            e1 += vv[nt][0]*tanh_ap(c[mt][nt][2] + ub[nt][0]);
            e1 += vv[nt][1]*tanh_ap(c[mt][nt][3] + ub[nt][1]);
        }
        e0 += __shfl_xor_sync(0xffffffffu, e0, 1);
        e0 += __shfl_xor_sync(0xffffffffu, e0, 2);
        e1 += __shfl_xor_sync(0xffffffffu, e1, 1);
        e1 += __shfl_xor_sync(0xffffffffu, e1, 2);
        if (tig == 0) {
            atomicAdd(&s_e[m_base + mt*16 + g],     e0);
            atomicAdd(&s_e[m_base + mt*16 + g + 8], e1);
        }
    }
    __syncthreads();
    if (tid < 128)
        g_energy2[(size_t)blockIdx.x*BS + row0 + tid] = s_e[tid];
}

// ---------------- softmax over S per batch (sums 2 coltile slices) ----------------
__global__ void k_softmax(float* __restrict__ attn) {
    const int b = blockIdx.x;
    const int tid = threadIdx.x;             // 256
    __shared__ float red[256];
    float v[8];
    float mx = -1e30f;
    #pragma unroll
    for (int i = 0; i < 8; i++) {
        int idx = b*Ss + tid + i*256;
        v[i] = g_energy2[idx] + g_energy2[BS + idx];
        mx = fmaxf(mx, v[i]);
    }
    red[tid] = mx; __syncthreads();
    for (int o = 128; o > 0; o >>= 1) {
        if (tid < o) red[tid] = fmaxf(red[tid], red[tid+o]);
        __syncthreads();
    }
    mx = red[0]; __syncthreads();
    float sum = 0.f;
    #pragma unroll
    for (int i = 0; i < 8; i++) { v[i] = __expf(v[i] - mx); sum += v[i]; }
    red[tid] = sum; __syncthreads();
    for (int o = 128; o > 0; o >>= 1) {
        if (tid < o) red[tid] += red[tid+o];
        __syncthreads();
    }
    float inv = 1.f / red[0];
    #pragma unroll
    for (int i = 0; i < 8; i++)
        attn[b*Ss + tid + i*256] = v[i] * inv;
}

// ---------------- context = attn @ enc (fp16 enc, fp32 accumulate) ----------------
__global__ void k_ctx_part(const float* __restrict__ attn) {
    const int sc = blockIdx.x;               // 0..15
    const int b  = blockIdx.y;
    const int tid = threadIdx.x;             // 256 = 4 grp x 64
    const int grp = tid >> 6;
    const int h0 = (tid & 63) * 8;
    const int s0 = sc * 128;
    const float* ab = attn + b*Ss + s0;
    const __half* eb = g_ench + ((size_t)(b*Ss + s0))*Hh + h0;
    float acc[8] = {0.f,0.f,0.f,0.f,0.f,0.f,0.f,0.f};
    #pragma unroll 4
    for (int i = 0; i < 32; i++) {
        int s = i*4 + grp;
        float w = ab[s];
        uint4 raw = *reinterpret_cast<const uint4*>(eb + (size_t)s*Hh);
        const __half2* hp = reinterpret_cast<const __half2*>(&raw);
        #pragma unroll
        for (int j = 0; j < 4; j++) {
            float2 f = __half22float2(hp[j]);
            acc[2*j]   += w * f.x;
            acc[2*j+1] += w * f.y;
        }
    }
    float* dst = g_ctx + ((size_t)(b*64 + sc*4 + grp))*Hh + h0;
    #pragma unroll
    for (int j = 0; j < 8; j++) dst[j] = acc[j];
}

__global__ void k_ctx_reduce(float* __restrict__ ctx) {
    const int b = blockIdx.x;
    const int h = threadIdx.x;               // 512
    float s = 0.f;
    #pragma unroll
    for (int p = 0; p < 64; p++)
        s += g_ctx[((size_t)(b*64 + p))*Hh + h];
    ctx[b*Hh + h] = s;
}

// ---------------- launch ----------------
extern "C" void kernel_launch(void* const* d_in, const int* in_sizes, int n_in,
                              void* d_out, int out_size) {
    const float* hidden = (const float*)d_in[0];
    const float* enc    = (const float*)d_in[1];
    const float* U_w    = (const float*)d_in[2];
    const float* U_b    = (const float*)d_in[3];
    const float* W_w    = (const float*)d_in[4];
    const float* W_b    = (const float*)d_in[5];
    const float* V_w    = (const float*)d_in[6];
    // V_b shifts all energies equally -> softmax invariant -> unused.

    float* out_ctx  = (float*)d_out;            // [B,H]
    float* out_attn = out_ctx + Bb*Hh;          // [B,S]

    cudaFuncSetAttribute(k_energy,
                         cudaFuncAttributeMaxDynamicSharedMemorySize, SMEM_TOTAL);

    unsigned cvt_blocks = (unsigned)(((size_t)BS * Hh) / 8u / 256u);  // 32768
    k_cvt_enc<<<cvt_blocks, 256>>>(enc);
    k_cvt_W<<<Hh*Hh/8/256, 256>>>(W_w);
    k_ubb<<<Bb, Hh>>>(hidden, U_w, U_b, W_b);
    k_energy<<<dim3(2, BS/128), 512, SMEM_TOTAL>>>(V_w);
    k_softmax<<<Bb, 256>>>(out_attn);
    k_ctx_part<<<dim3(16, Bb), 256>>>(out_attn);
    k_ctx_reduce<<<Bb, Hh>>>(out_ctx);
}

// round 8
// speedup vs baseline: 3.7716x; 1.0045x over previous
#include <cuda_runtime.h>
#include <cuda_fp16.h>
#include <cstdint>

#define Hh 512
#define Bb 64
#define Ss 2048
#define BS (Bb*Ss)   // 131072 rows

// ---------------- device scratch (no cudaMalloc allowed) ----------------
__device__ __half g_ench[(size_t)BS*Hh];   // enc in fp16 (128 MB)
__device__ __half g_Wh[Hh*Hh];             // W_w in fp16
__device__ float g_ubb[Bb*Hh];             // u + U_b + W_b per (b,h)
__device__ float g_energy8[8*BS];          // per-coltile energy partials
__device__ float g_ctx[Bb*64*Hh];          // context partials (16 sc x 4 grp)

// ---------------- generic PTX helpers ----------------
__device__ __forceinline__ void cpasync16(uint32_t dst, const void* src) {
    asm volatile("cp.async.cg.shared.global [%0], [%1], 16;\n"
                 :: "r"(dst), "l"(src));
}
__device__ __forceinline__ void cp_commit() {
    asm volatile("cp.async.commit_group;\n" ::: "memory");
}
template<int N> __device__ __forceinline__ void cp_wait() {
    asm volatile("cp.async.wait_group %0;\n" :: "n"(N) : "memory");
}
__device__ __forceinline__ uint32_t smem_u32(const void* p) {
    uint32_t a;
    asm("{ .reg .u64 t; cvta.to.shared.u64 t, %1; cvt.u32.u64 %0, t; }"
        : "=r"(a) : "l"(p));
    return a;
}
__device__ __forceinline__ float tanh_ap(float x) {
    float y;
    asm("tanh.approx.f32 %0, %1;" : "=f"(y) : "f"(x));
    return y;
}
__device__ __forceinline__ void ldsm_x4(uint32_t* r, uint32_t addr) {
    asm volatile("ldmatrix.sync.aligned.m8n8.x4.shared.b16 {%0,%1,%2,%3}, [%4];"
                 : "=r"(r[0]), "=r"(r[1]), "=r"(r[2]), "=r"(r[3]) : "r"(addr));
}
__device__ __forceinline__ void mma_f16(float* c, const uint32_t* a,
                                        uint32_t b0, uint32_t b1) {
    asm volatile(
        "mma.sync.aligned.m16n8k16.row.col.f32.f16.f16.f32 "
        "{%0,%1,%2,%3}, {%4,%5,%6,%7}, {%8,%9}, {%0,%1,%2,%3};"
        : "+f"(c[0]), "+f"(c[1]), "+f"(c[2]), "+f"(c[3])
        : "r"(a[0]), "r"(a[1]), "r"(a[2]), "r"(a[3]), "r"(b0), "r"(b1));
}

// SMEM: A 2 stages x 16KB ([blk4][row128][32B xor-swizzled]),
//       B 2 stages x 8KB  ([blk4][n64][32B xor-swizzled])
#define SMA_STAGE 16384u
#define SMB_OFF   32768u
#define SMB_STAGE 8192u
#define SMEM_TOTAL (32768 + 2*8192)   // 49152 per CTA

// ---------------- converts ----------------
__global__ void k_cvt_enc(const float* __restrict__ enc) {
    size_t i = ((size_t)blockIdx.x*blockDim.x + threadIdx.x) * 8;
    const float4* s = reinterpret_cast<const float4*>(enc + i);
    float4 v0 = s[0], v1 = s[1];
    __half2 h[4];
    h[0] = __floats2half2_rn(v0.x, v0.y);
    h[1] = __floats2half2_rn(v0.z, v0.w);
    h[2] = __floats2half2_rn(v1.x, v1.y);
    h[3] = __floats2half2_rn(v1.z, v1.w);
    *reinterpret_cast<uint4*>(g_ench + i) = *reinterpret_cast<uint4*>(h);
}
__global__ void k_cvt_W(const float* __restrict__ W) {
    size_t i = ((size_t)blockIdx.x*blockDim.x + threadIdx.x) * 8;
    const float4* s = reinterpret_cast<const float4*>(W + i);
    float4 v0 = s[0], v1 = s[1];
    __half2 h[4];
    h[0] = __floats2half2_rn(v0.x, v0.y);
    h[1] = __floats2half2_rn(v0.z, v0.w);
    h[2] = __floats2half2_rn(v1.x, v1.y);
    h[3] = __floats2half2_rn(v1.z, v1.w);
    *reinterpret_cast<uint4*>(g_Wh + i) = *reinterpret_cast<uint4*>(h);
}

// ---------------- prep: ubb = U(h) + U_b + W_b ----------------
__global__ void k_ubb(const float* __restrict__ hid,
                      const float* __restrict__ Uw,
                      const float* __restrict__ Ub,
                      const float* __restrict__ Wb) {
    int b = blockIdx.x;
    int h = threadIdx.x;
    __shared__ float hs[Hh];
    hs[h] = hid[b*Hh + h];
    __syncthreads();
    const float4* row = reinterpret_cast<const float4*>(Uw + (size_t)h*Hh);
    const float4* hv  = reinterpret_cast<const float4*>(hs);
    float acc = 0.f;
    #pragma unroll 4
    for (int k = 0; k < Hh/4; k++) {
        float4 r = row[k]; float4 x = hv[k];
        acc += r.x*x.x + r.y*x.y + r.z*x.z + r.w*x.w;
    }
    g_ubb[b*Hh + h] = acc + Ub[h] + Wb[h];
}

// ---------------- main: fp16 mma, CTA M128xN64, 3 CTAs/SM ----------------
// 256 threads / 8 warps: warp_m = wid&3 (m32), warp_n = wid>>2 (n32).
// grid (8 coltiles, 1024 rowtiles): 8 launch-adjacent CTAs share the A tile (L2),
// W (512KB fp16) stays fully L2-resident.

__device__ __forceinline__ void load_chunk(uint32_t sb, int row0, int col0,
                                           int kc, int stage, int tid) {
    uint32_t abase = sb + (uint32_t)stage * SMA_STAGE;
    uint32_t bbase = sb + SMB_OFF + (uint32_t)stage * SMB_STAGE;
    #pragma unroll
    for (int i = 0; i < 4; i++) {            // A: 1024 x 16B
        int u = tid + i*256;
        int blk = u >> 8, v = u & 255, r = v >> 1, c16 = v & 1;
        int p16 = c16 ^ ((r >> 2) & 1);
        cpasync16(abase + (uint32_t)(blk*4096 + r*32 + p16*16),
                  g_ench + (size_t)(row0 + r)*Hh + kc + blk*16 + c16*8);
    }
    #pragma unroll
    for (int i = 0; i < 2; i++) {            // B: 512 x 16B (64 n-rows)
        int u = tid + i*256;
        int blk = u >> 7, v = u & 127, n = v >> 1, c16 = v & 1;
        int p16 = c16 ^ ((n >> 2) & 1);
        cpasync16(bbase + (uint32_t)(blk*2048 + n*32 + p16*16),
                  g_Wh + (size_t)(col0 + n)*Hh + kc + blk*16 + c16*8);
    }
    cp_commit();
}

__global__ void __launch_bounds__(256, 3)
k_energy(const float* __restrict__ Vw) {
    extern __shared__ char smem[];
    uint32_t sb = smem_u32(smem);
    const int tid = threadIdx.x;
    const int wid = tid >> 5, lane = tid & 31;
    const int g = lane >> 2, tig = lane & 3;
    const int warp_m = wid & 3, warp_n = wid >> 2;
    const int m_base = warp_m * 32;
    const int n_base = warp_n * 32;

    const int col0 = blockIdx.x * 64;
    const int row0 = blockIdx.y * 128;       // never spans a batch
    const int b = row0 / Ss;

    // ldmatrix lane addresses (xor-swizzled 16B chunks in 32B rows)
    const int a_row = m_base + (lane & 15);
    const uint32_t a_sw = (uint32_t)(((lane >> 4) ^ (a_row >> 2)) & 1);
    const uint32_t a_off = (uint32_t)(a_row*32) + a_sw*16;
    const int b_nrow = n_base + (lane & 7) + ((lane >> 1) & 8);
    const uint32_t b_sw = (uint32_t)(((lane >> 3) ^ (b_nrow >> 2)) & 1);
    const uint32_t b_off = (uint32_t)(b_nrow*32) + b_sw*16;

    float c[2][4][4];
    #pragma unroll
    for (int mt = 0; mt < 2; mt++)
        #pragma unroll
        for (int nt = 0; nt < 4; nt++)
            #pragma unroll
            for (int j = 0; j < 4; j++) c[mt][nt][j] = 0.f;

    load_chunk(sb, row0, col0, 0,  0, tid);
    load_chunk(sb, row0, col0, 64, 1, tid);

    for (int ch = 0; ch < 8; ch++) {
        if (ch < 6) cp_wait<1>(); else cp_wait<0>();
        __syncthreads();

        const uint32_t As = sb + (uint32_t)(ch & 1)*SMA_STAGE;
        const uint32_t Bs = sb + SMB_OFF + (uint32_t)(ch & 1)*SMB_STAGE;

        #pragma unroll
        for (int blk = 0; blk < 4; blk++) {
            uint32_t a[2][4];
            ldsm_x4(a[0], As + blk*4096u + a_off);
            ldsm_x4(a[1], As + blk*4096u + a_off + 512u);
            uint32_t bf[4][2];
            #pragma unroll
            for (int p = 0; p < 2; p++) {
                uint32_t r[4];
                ldsm_x4(r, Bs + blk*2048u + b_off + (uint32_t)p*512u);
                bf[2*p][0]   = r[0]; bf[2*p][1]   = r[1];
                bf[2*p+1][0] = r[2]; bf[2*p+1][1] = r[3];
            }
            #pragma unroll
            for (int mt = 0; mt < 2; mt++)
                #pragma unroll
                for (int nt = 0; nt < 4; nt++)
                    mma_f16(c[mt][nt], a[mt], bf[nt][0], bf[nt][1]);
        }
        __syncthreads();
        if (ch + 2 < 8)
            load_chunk(sb, row0, col0, (ch + 2)*64, ch & 1, tid);
    }

    // fused epilogue: partial energy over this CTA's 64 cols, combined in smem
    __syncthreads();
    float* s_e = reinterpret_cast<float*>(smem);
    if (tid < 128) s_e[tid] = 0.f;
    __syncthreads();

    float ub[4][2], vv[4][2];
    #pragma unroll
    for (int nt = 0; nt < 4; nt++) {
        int cb = col0 + n_base + nt*8 + 2*tig;
        ub[nt][0] = g_ubb[b*Hh + cb];     ub[nt][1] = g_ubb[b*Hh + cb + 1];
        vv[nt][0] = Vw[cb];               vv[nt][1] = Vw[cb + 1];
    }
    #pragma unroll
    for (int mt = 0; mt < 2; mt++) {
        float e0 = 0.f, e1 = 0.f;
        #pragma unroll
        for (int nt = 0; nt < 4; nt++) {
            e0 += vv[nt][0]*tanh_ap(c[mt][nt][0] + ub[nt][0]);
            e0 += vv[nt][1]*tanh_ap(c[mt][nt][1] + ub[nt][1]);
            e1 += vv[nt][0]*tanh_ap(c[mt][nt][2] + ub[nt][0]);
            e1 += vv[nt][1]*tanh_ap(c[mt][nt][3] + ub[nt][1]);
        }
        e0 += __shfl_xor_sync(0xffffffffu, e0, 1);
        e0 += __shfl_xor_sync(0xffffffffu, e0, 2);
        e1 += __shfl_xor_sync(0xffffffffu, e1, 1);
        e1 += __shfl_xor_sync(0xffffffffu, e1, 2);
        if (tig == 0) {
            atomicAdd(&s_e[m_base + mt*16 + g],     e0);
            atomicAdd(&s_e[m_base + mt*16 + g + 8], e1);
        }
    }
    __syncthreads();
    if (tid < 128)
        g_energy8[(size_t)blockIdx.x*BS + row0 + tid] = s_e[tid];
}

// ---------------- softmax over S per batch (sums 8 coltile slices) ----------------
__global__ void k_softmax(float* __restrict__ attn) {
    const int b = blockIdx.x;
    const int tid = threadIdx.x;             // 256
    __shared__ float red[256];
    float v[8];
    float mx = -1e30f;
    #pragma unroll
    for (int i = 0; i < 8; i++) {
        int idx = b*Ss + tid + i*256;
        float s = 0.f;
        #pragma unroll
        for (int t = 0; t < 8; t++) s += g_energy8[(size_t)t*BS + idx];
        v[i] = s;
        mx = fmaxf(mx, v[i]);
    }
    red[tid] = mx; __syncthreads();
    for (int o = 128; o > 0; o >>= 1) {
        if (tid < o) red[tid] = fmaxf(red[tid], red[tid+o]);
        __syncthreads();
    }
    mx = red[0]; __syncthreads();
    float sum = 0.f;
    #pragma unroll
    for (int i = 0; i < 8; i++) { v[i] = __expf(v[i] - mx); sum += v[i]; }
    red[tid] = sum; __syncthreads();
    for (int o = 128; o > 0; o >>= 1) {
        if (tid < o) red[tid] += red[tid+o];
        __syncthreads();
    }
    float inv = 1.f / red[0];
    #pragma unroll
    for (int i = 0; i < 8; i++)
        attn[b*Ss + tid + i*256] = v[i] * inv;
}

// ---------------- context = attn @ enc (fp16 enc, fp32 accumulate) ----------------
__global__ void k_ctx_part(const float* __restrict__ attn) {
    const int sc = blockIdx.x;               // 0..15
    const int b  = blockIdx.y;
    const int tid = threadIdx.x;             // 256 = 4 grp x 64
    const int grp = tid >> 6;
    const int h0 = (tid & 63) * 8;
    const int s0 = sc * 128;
    const float* ab = attn + b*Ss + s0;
    const __half* eb = g_ench + ((size_t)(b*Ss + s0))*Hh + h0;
    float acc[8] = {0.f,0.f,0.f,0.f,0.f,0.f,0.f,0.f};
    #pragma unroll 4
    for (int i = 0; i < 32; i++) {
        int s = i*4 + grp;
        float w = ab[s];
        uint4 raw = *reinterpret_cast<const uint4*>(eb + (size_t)s*Hh);
        const __half2* hp = reinterpret_cast<const __half2*>(&raw);
        #pragma unroll
        for (int j = 0; j < 4; j++) {
            float2 f = __half22float2(hp[j]);
            acc[2*j]   += w * f.x;
            acc[2*j+1] += w * f.y;
        }
    }
    float* dst = g_ctx + ((size_t)(b*64 + sc*4 + grp))*Hh + h0;
    #pragma unroll
    for (int j = 0; j < 8; j++) dst[j] = acc[j];
}

__global__ void k_ctx_reduce(float* __restrict__ ctx) {
    const int b = blockIdx.x;
    const int h = threadIdx.x;               // 512
    float s = 0.f;
    #pragma unroll
    for (int p = 0; p < 64; p++)
        s += g_ctx[((size_t)(b*64 + p))*Hh + h];
    ctx[b*Hh + h] = s;
}

// ---------------- launch ----------------
extern "C" void kernel_launch(void* const* d_in, const int* in_sizes, int n_in,
                              void* d_out, int out_size) {
    const float* hidden = (const float*)d_in[0];
    const float* enc    = (const float*)d_in[1];
    const float* U_w    = (const float*)d_in[2];
    const float* U_b    = (const float*)d_in[3];
    const float* W_w    = (const float*)d_in[4];
    const float* W_b    = (const float*)d_in[5];
    const float* V_w    = (const float*)d_in[6];
    // V_b shifts all energies equally -> softmax invariant -> unused.

    float* out_ctx  = (float*)d_out;            // [B,H]
    float* out_attn = out_ctx + Bb*Hh;          // [B,S]

    cudaFuncSetAttribute(k_energy,
                         cudaFuncAttributeMaxDynamicSharedMemorySize, SMEM_TOTAL);

    unsigned cvt_blocks = (unsigned)(((size_t)BS * Hh) / 8u / 256u);  // 32768
    k_cvt_enc<<<cvt_blocks, 256>>>(enc);
    k_cvt_W<<<Hh*Hh/8/256, 256>>>(W_w);
    k_ubb<<<Bb, Hh>>>(hidden, U_w, U_b, W_b);
    k_energy<<<dim3(8, BS/128), 256, SMEM_TOTAL>>>(V_w);
    k_softmax<<<Bb, 256>>>(out_attn);
    k_ctx_part<<<dim3(16, Bb), 256>>>(out_attn);
    k_ctx_reduce<<<Bb, Hh>>>(out_ctx);
}